// round 3
// baseline (speedup 1.0000x reference)
#include <cuda_runtime.h>
#include <math.h>
#include <stdint.h>

// Problem constants
#define S_   100
#define U_   128
#define H_   256
#define V_   10000
#define H3_  768
#define MTOT (S_ * U_)        // 12800
#define KFC  (2 * H_)         // 512

// Scratch (device globals; no dynamic allocation allowed)
__device__ float g_GI[MTOT * H3_];      // (S*U, 3H) input-side gates
__device__ float g_out[MTOT * H_];      // (S, U, H) GRU outputs
__device__ float g_A[(size_t)MTOT * KFC]; // (S*U, 512) concat [out_w | p_u]

// ---------------------------------------------------------------------------
// Kernel 1: GI = gather(enc_W, x) @ W_ih^T + b_ih
// M=12800, N=768, K=256.  64x64 tile, 256 threads, 4x4 micro-tile.
// ---------------------------------------------------------------------------
__global__ __launch_bounds__(256) void k_gi(
    const int* __restrict__ x,
    const float* __restrict__ enc_W,
    const float* __restrict__ W_ih,
    const float* __restrict__ b_ih)
{
    __shared__ float As[16][68];
    __shared__ float Bs[16][68];
    __shared__ int rowIdx[64];

    const int tid = threadIdx.x;
    const int mBase = blockIdx.x * 64;
    const int nBase = blockIdx.y * 64;

    if (tid < 64) rowIdx[tid] = x[mBase + tid];
    __syncthreads();

    const int tr = tid / 16;   // 0..15
    const int tc = tid % 16;   // 0..15
    const int lr = tid / 4;    // load row 0..63
    const int lq = tid % 4;    // load quad 0..3

    float acc[4][4];
#pragma unroll
    for (int r = 0; r < 4; ++r)
#pragma unroll
        for (int c = 0; c < 4; ++c) acc[r][c] = 0.f;

    const int arow = rowIdx[lr];

    for (int k0 = 0; k0 < H_; k0 += 16) {
        float4 av = *(const float4*)(enc_W + (size_t)arow * H_ + k0 + lq * 4);
        float4 bv = *(const float4*)(W_ih + (size_t)(nBase + lr) * H_ + k0 + lq * 4);
        __syncthreads();
        As[lq * 4 + 0][lr] = av.x; As[lq * 4 + 1][lr] = av.y;
        As[lq * 4 + 2][lr] = av.z; As[lq * 4 + 3][lr] = av.w;
        Bs[lq * 4 + 0][lr] = bv.x; Bs[lq * 4 + 1][lr] = bv.y;
        Bs[lq * 4 + 2][lr] = bv.z; Bs[lq * 4 + 3][lr] = bv.w;
        __syncthreads();
#pragma unroll
        for (int k = 0; k < 16; ++k) {
            float a[4], b[4];
#pragma unroll
            for (int r = 0; r < 4; ++r) a[r] = As[k][tr * 4 + r];
#pragma unroll
            for (int c = 0; c < 4; ++c) b[c] = Bs[k][tc * 4 + c];
#pragma unroll
            for (int r = 0; r < 4; ++r)
#pragma unroll
                for (int c = 0; c < 4; ++c) acc[r][c] += a[r] * b[c];
        }
    }

#pragma unroll
    for (int r = 0; r < 4; ++r) {
        const int m = mBase + tr * 4 + r;
        float* row = g_GI + (size_t)m * H3_;
#pragma unroll
        for (int c = 0; c < 4; ++c) {
            const int n = nBase + tc * 4 + c;
            row[n] = acc[r][c] + b_ih[n];
        }
    }
}

// ---------------------------------------------------------------------------
// Kernel 2: GRU scan. Users are fully independent -> each block owns 4 users
// for the whole 100-step recurrence with h held in SMEM. 32 blocks x 256 thr.
// ---------------------------------------------------------------------------
__global__ __launch_bounds__(256) void k_gru(
    const float* __restrict__ h0,     // (U, H)
    const float* __restrict__ W_hh,   // (3H, H)
    const float* __restrict__ b_hh)   // (3H)
{
    const int u0 = blockIdx.x * 4;
    const int tid = threadIdx.x;

    __shared__ float hs[4][H_];    // 4 KB
    __shared__ float ghs[4][H3_];  // 12 KB

    for (int i = tid; i < 4 * H_; i += 256) {
        const int u = i / H_, k = i % H_;
        hs[u][k] = h0[(size_t)(u0 + u) * H_ + k];
    }
    __syncthreads();

    const float4* W0 = (const float4*)(W_hh + (size_t)(tid)       * H_);
    const float4* W1 = (const float4*)(W_hh + (size_t)(tid + 256) * H_);
    const float4* W2 = (const float4*)(W_hh + (size_t)(tid + 512) * H_);
    const float bh0 = b_hh[tid], bh1 = b_hh[tid + 256], bh2 = b_hh[tid + 512];

    const int uu = tid >> 6;          // phase-2 user 0..3
    const int kk = (tid & 63) * 4;    // phase-2 k (float4)

    for (int t = 0; t < S_; ++t) {
        // ---- phase 1: gh = h @ W_hh^T + b_hh (thread = 3 gates x 4 users)
        float a0[4], a1[4], a2[4];
#pragma unroll
        for (int u = 0; u < 4; ++u) { a0[u] = 0.f; a1[u] = 0.f; a2[u] = 0.f; }

#pragma unroll 4
        for (int k4 = 0; k4 < H_ / 4; ++k4) {
            float4 w0 = W0[k4], w1 = W1[k4], w2 = W2[k4];
#pragma unroll
            for (int u = 0; u < 4; ++u) {
                float4 h4 = *(const float4*)&hs[u][k4 * 4];
                a0[u] += w0.x * h4.x + w0.y * h4.y + w0.z * h4.z + w0.w * h4.w;
                a1[u] += w1.x * h4.x + w1.y * h4.y + w1.z * h4.z + w1.w * h4.w;
                a2[u] += w2.x * h4.x + w2.y * h4.y + w2.z * h4.z + w2.w * h4.w;
            }
        }
#pragma unroll
        for (int u = 0; u < 4; ++u) {
            ghs[u][tid]       = a0[u] + bh0;
            ghs[u][tid + 256] = a1[u] + bh1;
            ghs[u][tid + 512] = a2[u] + bh2;
        }
        __syncthreads();

        // ---- phase 2: gate nonlinearity + h update (thread = 4 floats, 1 user)
        const float* GIrow = g_GI + ((size_t)t * U_ + (u0 + uu)) * H3_;
        float4 ir = *(const float4*)(GIrow + kk);
        float4 iz = *(const float4*)(GIrow + H_ + kk);
        float4 in4 = *(const float4*)(GIrow + 2 * H_ + kk);
        float4 hr = *(const float4*)&ghs[uu][kk];
        float4 hz = *(const float4*)&ghs[uu][H_ + kk];
        float4 hn = *(const float4*)&ghs[uu][2 * H_ + kk];
        float4 hp = *(const float4*)&hs[uu][kk];

        float4 hnew;
        {
            float r = 1.f / (1.f + expf(-(ir.x + hr.x)));
            float z = 1.f / (1.f + expf(-(iz.x + hz.x)));
            float n = tanhf(in4.x + r * hn.x);
            hnew.x = (1.f - z) * n + z * hp.x;
        }
        {
            float r = 1.f / (1.f + expf(-(ir.y + hr.y)));
            float z = 1.f / (1.f + expf(-(iz.y + hz.y)));
            float n = tanhf(in4.y + r * hn.y);
            hnew.y = (1.f - z) * n + z * hp.y;
        }
        {
            float r = 1.f / (1.f + expf(-(ir.z + hr.z)));
            float z = 1.f / (1.f + expf(-(iz.z + hz.z)));
            float n = tanhf(in4.z + r * hn.z);
            hnew.z = (1.f - z) * n + z * hp.z;
        }
        {
            float r = 1.f / (1.f + expf(-(ir.w + hr.w)));
            float z = 1.f / (1.f + expf(-(iz.w + hz.w)));
            float n = tanhf(in4.w + r * hn.w);
            hnew.w = (1.f - z) * n + z * hp.w;
        }

        *(float4*)&hs[uu][kk] = hnew;
        *(float4*)(g_out + ((size_t)t * U_ + (u0 + uu)) * H_ + kk) = hnew;
        __syncthreads();
    }
}

// ---------------------------------------------------------------------------
// Kernel 3: causal spatio-temporal weights + weighted sum; builds A = [out_w|p_u]
// Block per (i, u), 128 threads.
// ---------------------------------------------------------------------------
__global__ __launch_bounds__(128) void k_outw(
    const float* __restrict__ t_in,        // (S, U)
    const float* __restrict__ s_in,        // (S, U, 2)
    const int* __restrict__ active_user,   // (U)
    const float* __restrict__ user_W)      // (UC, H)
{
    const int i = blockIdx.x;
    const int u = blockIdx.y;
    const int tid = threadIdx.x;

    __shared__ float w[S_];

    const float ti = t_in[i * U_ + u];
    const float si0 = s_in[(i * U_ + u) * 2 + 0];
    const float si1 = s_in[(i * U_ + u) * 2 + 1];

    if (tid <= i && tid < S_) {
        const int j = tid;
        const float dt = ti - t_in[j * U_ + u];
        const float dx = si0 - s_in[(j * U_ + u) * 2 + 0];
        const float dy = si1 - s_in[(j * U_ + u) * 2 + 1];
        const float dist = sqrtf(dx * dx + dy * dy);
        const float a = (cosf(dt * (6.2831853071795864f / 86400.f)) + 1.f) * 0.5f
                        * expf(dt * (-0.1f / 86400.f));
        const float b = expf(-dist * 100.f);
        w[j] = a * b + 1e-10f;
    }
    __syncthreads();

    float sum = 0.f;
    for (int j = 0; j <= i; ++j) sum += w[j];   // broadcast reads, cheap
    const float inv = 1.f / sum;

    float acc0 = 0.f, acc1 = 0.f;
    for (int j = 0; j <= i; ++j) {
        const float wj = w[j];
        const float* orow = g_out + ((size_t)j * U_ + u) * H_;
        acc0 += wj * orow[tid];
        acc1 += wj * orow[tid + 128];
    }

    const size_t m = (size_t)i * U_ + u;
    float* arow = g_A + m * KFC;
    arow[tid]       = acc0 * inv;
    arow[tid + 128] = acc1 * inv;

    const float* pu = user_W + (size_t)active_user[u] * H_;
    arow[256 + tid]       = pu[tid];
    arow[256 + 128 + tid] = pu[tid + 128];
}

// ---------------------------------------------------------------------------
// Kernel 4: y = A @ fc_W^T + fc_b.  M=12800, N=10000, K=512.
// 128x128 tile, 256 threads, 8x8 micro (split-tile 4+4 layout for bank-friendly
// LDS.128), BK=16.
// ---------------------------------------------------------------------------
__global__ __launch_bounds__(256) void k_fc(
    const float* __restrict__ fc_W,   // (V, 512)
    const float* __restrict__ fc_b,   // (V)
    float* __restrict__ out)          // (S*U, V)
{
    __shared__ float As[16][132];
    __shared__ float Bs[16][132];

    const int tid = threadIdx.x;
    const int mBase = blockIdx.x * 128;
    const int nBase = blockIdx.y * 128;

    const int tr = tid / 16;   // 0..15
    const int tc = tid % 16;   // 0..15

    const int lr0 = tid / 4;          // 0..63
    const int lr1 = lr0 + 64;         // 64..127
    const int lq = tid % 4;           // 0..3

    float acc[8][8];
#pragma unroll
    for (int r = 0; r < 8; ++r)
#pragma unroll
        for (int c = 0; c < 8; ++c) acc[r][c] = 0.f;

    const float* Abase = g_A + (size_t)mBase * KFC;
    const int n0 = nBase + lr0;
    const int n1 = nBase + lr1;
    const float4 z4 = make_float4(0.f, 0.f, 0.f, 0.f);

    for (int k0 = 0; k0 < KFC; k0 += 16) {
        float4 av0 = *(const float4*)(Abase + (size_t)lr0 * KFC + k0 + lq * 4);
        float4 av1 = *(const float4*)(Abase + (size_t)lr1 * KFC + k0 + lq * 4);
        float4 bv0 = (n0 < V_) ? *(const float4*)(fc_W + (size_t)n0 * KFC + k0 + lq * 4) : z4;
        float4 bv1 = (n1 < V_) ? *(const float4*)(fc_W + (size_t)n1 * KFC + k0 + lq * 4) : z4;
        __syncthreads();
        As[lq * 4 + 0][lr0] = av0.x; As[lq * 4 + 1][lr0] = av0.y;
        As[lq * 4 + 2][lr0] = av0.z; As[lq * 4 + 3][lr0] = av0.w;
        As[lq * 4 + 0][lr1] = av1.x; As[lq * 4 + 1][lr1] = av1.y;
        As[lq * 4 + 2][lr1] = av1.z; As[lq * 4 + 3][lr1] = av1.w;
        Bs[lq * 4 + 0][lr0] = bv0.x; Bs[lq * 4 + 1][lr0] = bv0.y;
        Bs[lq * 4 + 2][lr0] = bv0.z; Bs[lq * 4 + 3][lr0] = bv0.w;
        Bs[lq * 4 + 0][lr1] = bv1.x; Bs[lq * 4 + 1][lr1] = bv1.y;
        Bs[lq * 4 + 2][lr1] = bv1.z; Bs[lq * 4 + 3][lr1] = bv1.w;
        __syncthreads();
#pragma unroll
        for (int k = 0; k < 16; ++k) {
            float a[8], b[8];
            // split-tile: rows tr*4..tr*4+3 and 64+tr*4..; cols likewise
            *(float4*)&a[0] = *(const float4*)&As[k][tr * 4];
            *(float4*)&a[4] = *(const float4*)&As[k][64 + tr * 4];
            *(float4*)&b[0] = *(const float4*)&Bs[k][tc * 4];
            *(float4*)&b[4] = *(const float4*)&Bs[k][64 + tc * 4];
#pragma unroll
            for (int r = 0; r < 8; ++r)
#pragma unroll
                for (int c = 0; c < 8; ++c) acc[r][c] += a[r] * b[c];
        }
    }

    // epilogue
    float bias[8];
#pragma unroll
    for (int c = 0; c < 8; ++c) {
        const int n = nBase + ((c < 4) ? (tc * 4 + c) : (64 + tc * 4 + c - 4));
        bias[c] = (n < V_) ? fc_b[n] : 0.f;
    }
#pragma unroll
    for (int r = 0; r < 8; ++r) {
        const int m = mBase + ((r < 4) ? (tr * 4 + r) : (64 + tr * 4 + r - 4));
        float* orow = out + (size_t)m * V_;
#pragma unroll
        for (int c = 0; c < 8; ++c) {
            const int n = nBase + ((c < 4) ? (tc * 4 + c) : (64 + tc * 4 + c - 4));
            if (n < V_) orow[n] = acc[r][c] + bias[c];
        }
    }
}

// ---------------------------------------------------------------------------
// Kernel 5: h_last -> tail of output (out[S*U*V .. +U*H])
// ---------------------------------------------------------------------------
__global__ void k_hlast(float* __restrict__ out)
{
    const int idx = blockIdx.x * blockDim.x + threadIdx.x;
    if (idx < U_ * H_)
        out[(size_t)S_ * U_ * V_ + idx] = g_out[(size_t)(S_ - 1) * U_ * H_ + idx];
}

// ---------------------------------------------------------------------------
// Launch
// ---------------------------------------------------------------------------
extern "C" void kernel_launch(void* const* d_in, const int* in_sizes, int n_in,
                              void* d_out, int out_size)
{
    (void)in_sizes; (void)n_in; (void)out_size;
    const int*   x      = (const int*)  d_in[0];
    const float* t_in   = (const float*)d_in[1];
    const float* s_in   = (const float*)d_in[2];
    // d_in[3] = y_t, d_in[4] = y_s : unused by forward
    const float* h0     = (const float*)d_in[5];
    const int*   au     = (const int*)  d_in[6];
    const float* enc_W  = (const float*)d_in[7];
    const float* user_W = (const float*)d_in[8];
    const float* W_ih   = (const float*)d_in[9];
    const float* W_hh   = (const float*)d_in[10];
    const float* b_ih   = (const float*)d_in[11];
    const float* b_hh   = (const float*)d_in[12];
    const float* fc_W   = (const float*)d_in[13];
    const float* fc_b   = (const float*)d_in[14];
    float* out = (float*)d_out;

    k_gi<<<dim3(MTOT / 64, H3_ / 64), 256>>>(x, enc_W, W_ih, b_ih);
    k_gru<<<U_ / 4, 256>>>(h0, W_hh, b_hh);
    k_hlast<<<(U_ * H_ + 255) / 256, 256>>>(out);
    k_outw<<<dim3(S_, U_), 128>>>(t_in, s_in, au, user_W);
    k_fc<<<dim3(MTOT / 128, (V_ + 127) / 128), 256>>>(fc_W, fc_b, out);
}

// round 6
// speedup vs baseline: 1.8129x; 1.8129x over previous
#include <cuda_runtime.h>
#include <math.h>
#include <stdint.h>

// Problem constants
#define S_   100
#define U_   128
#define H_   256
#define V_   10000
#define H3_  768
#define MTOT (S_ * U_)        // 12800
#define KFC  (2 * H_)         // 512

// Scratch (device globals; no dynamic allocation allowed)
__device__ float g_GI[MTOT * H3_];        // (S*U, 3H) input-side gates
__device__ float g_out[MTOT * H_];        // (S, U, H) GRU outputs
__device__ float g_A[(size_t)MTOT * KFC]; // (S*U, 512) concat [out_w | p_u]

// ---------------------------------------------------------------------------
// Helpers: packed f32x2 FMA (sm_100+), tf32 split, tf32 mma
// ---------------------------------------------------------------------------
__device__ __forceinline__ void fma2(unsigned long long& d,
                                     unsigned long long a,
                                     unsigned long long b)
{
    asm("fma.rn.f32x2 %0, %1, %2, %0;" : "+l"(d) : "l"(a), "l"(b));
}

__device__ __forceinline__ float hsum2(unsigned long long v)
{
    float lo, hi;
    asm("mov.b64 {%0,%1}, %2;" : "=f"(lo), "=f"(hi) : "l"(v));
    return lo + hi;
}

__device__ __forceinline__ void split_tf32(float a, uint32_t& hi, uint32_t& lo)
{
    uint32_t h;
    asm("cvt.rna.tf32.f32 %0, %1;" : "=r"(h) : "f"(a));
    float l = a - __uint_as_float(h);
    uint32_t lr;
    asm("cvt.rna.tf32.f32 %0, %1;" : "=r"(lr) : "f"(l));
    hi = h; lo = lr;
}

__device__ __forceinline__ void mma_tf32(float* d, const uint32_t* a, const uint32_t* b)
{
    asm volatile(
        "mma.sync.aligned.m16n8k8.row.col.f32.tf32.tf32.f32 "
        "{%0,%1,%2,%3}, {%4,%5,%6,%7}, {%8,%9}, {%0,%1,%2,%3};"
        : "+f"(d[0]), "+f"(d[1]), "+f"(d[2]), "+f"(d[3])
        : "r"(a[0]), "r"(a[1]), "r"(a[2]), "r"(a[3]), "r"(b[0]), "r"(b[1]));
}

// ---------------------------------------------------------------------------
// Kernel 1: GI = gather(enc_W, x) @ W_ih^T + b_ih
// M=12800, N=768, K=256.  64x64 tile, 256 threads, 4x4 micro-tile. (fp32)
// ---------------------------------------------------------------------------
__global__ __launch_bounds__(256) void k_gi(
    const int* __restrict__ x,
    const float* __restrict__ enc_W,
    const float* __restrict__ W_ih,
    const float* __restrict__ b_ih)
{
    __shared__ float As[16][68];
    __shared__ float Bs[16][68];
    __shared__ int rowIdx[64];

    const int tid = threadIdx.x;
    const int mBase = blockIdx.x * 64;
    const int nBase = blockIdx.y * 64;

    if (tid < 64) rowIdx[tid] = x[mBase + tid];
    __syncthreads();

    const int tr = tid / 16;
    const int tc = tid % 16;
    const int lr = tid / 4;
    const int lq = tid % 4;

    float acc[4][4];
#pragma unroll
    for (int r = 0; r < 4; ++r)
#pragma unroll
        for (int c = 0; c < 4; ++c) acc[r][c] = 0.f;

    const int arow = rowIdx[lr];

    for (int k0 = 0; k0 < H_; k0 += 16) {
        float4 av = *(const float4*)(enc_W + (size_t)arow * H_ + k0 + lq * 4);
        float4 bv = *(const float4*)(W_ih + (size_t)(nBase + lr) * H_ + k0 + lq * 4);
        __syncthreads();
        As[lq * 4 + 0][lr] = av.x; As[lq * 4 + 1][lr] = av.y;
        As[lq * 4 + 2][lr] = av.z; As[lq * 4 + 3][lr] = av.w;
        Bs[lq * 4 + 0][lr] = bv.x; Bs[lq * 4 + 1][lr] = bv.y;
        Bs[lq * 4 + 2][lr] = bv.z; Bs[lq * 4 + 3][lr] = bv.w;
        __syncthreads();
#pragma unroll
        for (int k = 0; k < 16; ++k) {
            float a[4], b[4];
#pragma unroll
            for (int r = 0; r < 4; ++r) a[r] = As[k][tr * 4 + r];
#pragma unroll
            for (int c = 0; c < 4; ++c) b[c] = Bs[k][tc * 4 + c];
#pragma unroll
            for (int r = 0; r < 4; ++r)
#pragma unroll
                for (int c = 0; c < 4; ++c) acc[r][c] += a[r] * b[c];
        }
    }

#pragma unroll
    for (int r = 0; r < 4; ++r) {
        const int m = mBase + tr * 4 + r;
        float* row = g_GI + (size_t)m * H3_;
#pragma unroll
        for (int c = 0; c < 4; ++c) {
            const int n = nBase + tc * 4 + c;
            row[n] = acc[r][c] + b_ih[n];
        }
    }
}

// ---------------------------------------------------------------------------
// Kernel 2: GRU scan. 32 blocks x 4 users; phase-1 GEMV uses packed f32x2 FMA
// over contiguous k-pairs (no packing overhead; horizontal sum at the end).
// ---------------------------------------------------------------------------
__global__ __launch_bounds__(256) void k_gru(
    const float* __restrict__ h0,     // (U, H)
    const float* __restrict__ W_hh,   // (3H, H)
    const float* __restrict__ b_hh)   // (3H)
{
    const int u0 = blockIdx.x * 4;
    const int tid = threadIdx.x;

    __shared__ float hs[4][H_];    // 4 KB
    __shared__ float ghs[4][H3_];  // 12 KB

    for (int i = tid; i < 4 * H_; i += 256) {
        const int u = i / H_, k = i % H_;
        hs[u][k] = h0[(size_t)(u0 + u) * H_ + k];
    }
    __syncthreads();

    const ulonglong2* W0 = (const ulonglong2*)(W_hh + (size_t)(tid)       * H_);
    const ulonglong2* W1 = (const ulonglong2*)(W_hh + (size_t)(tid + 256) * H_);
    const ulonglong2* W2 = (const ulonglong2*)(W_hh + (size_t)(tid + 512) * H_);
    const float bh0 = b_hh[tid], bh1 = b_hh[tid + 256], bh2 = b_hh[tid + 512];

    const int uu = tid >> 6;          // phase-2 user 0..3
    const int kk = (tid & 63) * 4;    // phase-2 k (float4)

    for (int t = 0; t < S_; ++t) {
        // ---- phase 1: gh = h @ W_hh^T + b_hh, packed f32x2 over k-pairs
        unsigned long long a0[4] = {0ull, 0ull, 0ull, 0ull};
        unsigned long long a1[4] = {0ull, 0ull, 0ull, 0ull};
        unsigned long long a2[4] = {0ull, 0ull, 0ull, 0ull};

#pragma unroll 4
        for (int k4 = 0; k4 < H_ / 4; ++k4) {
            ulonglong2 w0 = W0[k4], w1 = W1[k4], w2 = W2[k4];
#pragma unroll
            for (int u = 0; u < 4; ++u) {
                ulonglong2 h4 = *(const ulonglong2*)&hs[u][k4 * 4];
                fma2(a0[u], w0.x, h4.x); fma2(a0[u], w0.y, h4.y);
                fma2(a1[u], w1.x, h4.x); fma2(a1[u], w1.y, h4.y);
                fma2(a2[u], w2.x, h4.x); fma2(a2[u], w2.y, h4.y);
            }
        }
#pragma unroll
        for (int u = 0; u < 4; ++u) {
            ghs[u][tid]       = hsum2(a0[u]) + bh0;
            ghs[u][tid + 256] = hsum2(a1[u]) + bh1;
            ghs[u][tid + 512] = hsum2(a2[u]) + bh2;
        }
        __syncthreads();

        // ---- phase 2: gate nonlinearity + h update
        const float* GIrow = g_GI + ((size_t)t * U_ + (u0 + uu)) * H3_;
        float4 ir = *(const float4*)(GIrow + kk);
        float4 iz = *(const float4*)(GIrow + H_ + kk);
        float4 in4 = *(const float4*)(GIrow + 2 * H_ + kk);
        float4 hr = *(const float4*)&ghs[uu][kk];
        float4 hz = *(const float4*)&ghs[uu][H_ + kk];
        float4 hn = *(const float4*)&ghs[uu][2 * H_ + kk];
        float4 hp = *(const float4*)&hs[uu][kk];

        float4 hnew;
        {
            float r = 1.f / (1.f + expf(-(ir.x + hr.x)));
            float z = 1.f / (1.f + expf(-(iz.x + hz.x)));
            float n = tanhf(in4.x + r * hn.x);
            hnew.x = (1.f - z) * n + z * hp.x;
        }
        {
            float r = 1.f / (1.f + expf(-(ir.y + hr.y)));
            float z = 1.f / (1.f + expf(-(iz.y + hz.y)));
            float n = tanhf(in4.y + r * hn.y);
            hnew.y = (1.f - z) * n + z * hp.y;
        }
        {
            float r = 1.f / (1.f + expf(-(ir.z + hr.z)));
            float z = 1.f / (1.f + expf(-(iz.z + hz.z)));
            float n = tanhf(in4.z + r * hn.z);
            hnew.z = (1.f - z) * n + z * hp.z;
        }
        {
            float r = 1.f / (1.f + expf(-(ir.w + hr.w)));
            float z = 1.f / (1.f + expf(-(iz.w + hz.w)));
            float n = tanhf(in4.w + r * hn.w);
            hnew.w = (1.f - z) * n + z * hp.w;
        }

        *(float4*)&hs[uu][kk] = hnew;
        *(float4*)(g_out + ((size_t)t * U_ + (u0 + uu)) * H_ + kk) = hnew;
        __syncthreads();
    }
}

// ---------------------------------------------------------------------------
// Kernel 3: causal spatio-temporal weights + weighted sum -> A = [out_w | p_u]
// ---------------------------------------------------------------------------
__global__ __launch_bounds__(128) void k_outw(
    const float* __restrict__ t_in,        // (S, U)
    const float* __restrict__ s_in,        // (S, U, 2)
    const int* __restrict__ active_user,   // (U)
    const float* __restrict__ user_W)      // (UC, H)
{
    const int i = blockIdx.x;
    const int u = blockIdx.y;
    const int tid = threadIdx.x;

    __shared__ float w[S_];

    const float ti = t_in[i * U_ + u];
    const float si0 = s_in[(i * U_ + u) * 2 + 0];
    const float si1 = s_in[(i * U_ + u) * 2 + 1];

    if (tid <= i && tid < S_) {
        const int j = tid;
        const float dt = ti - t_in[j * U_ + u];
        const float dx = si0 - s_in[(j * U_ + u) * 2 + 0];
        const float dy = si1 - s_in[(j * U_ + u) * 2 + 1];
        const float dist = sqrtf(dx * dx + dy * dy);
        const float a = (cosf(dt * (6.2831853071795864f / 86400.f)) + 1.f) * 0.5f
                        * expf(dt * (-0.1f / 86400.f));
        const float b = expf(-dist * 100.f);
        w[j] = a * b + 1e-10f;
    }
    __syncthreads();

    float sum = 0.f;
    for (int j = 0; j <= i; ++j) sum += w[j];
    const float inv = 1.f / sum;

    float acc0 = 0.f, acc1 = 0.f;
    for (int j = 0; j <= i; ++j) {
        const float wj = w[j];
        const float* orow = g_out + ((size_t)j * U_ + u) * H_;
        acc0 += wj * orow[tid];
        acc1 += wj * orow[tid + 128];
    }

    const size_t m = (size_t)i * U_ + u;
    float* arow = g_A + m * KFC;
    arow[tid]       = acc0 * inv;
    arow[tid + 128] = acc1 * inv;

    const float* pu = user_W + (size_t)active_user[u] * H_;
    arow[256 + tid]       = pu[tid];
    arow[256 + 128 + tid] = pu[tid + 128];
}

// ---------------------------------------------------------------------------
// Kernel 4: y = A @ fc_W^T + fc_b via tensor cores (3xTF32 mma.sync).
// M=12800, N=10000, K=512. 128x128 block tile, BK=32, 8 warps x (64x32).
// SMEM padded to stride 36 floats -> conflict-free scalar fragment loads.
// ---------------------------------------------------------------------------
#define FC_LD 36

__global__ __launch_bounds__(256, 1) void k_fc_tc(
    const float* __restrict__ fc_W,   // (V, 512)
    const float* __restrict__ fc_b,   // (V)
    float* __restrict__ out)          // (S*U, V)
{
    __shared__ float As[128 * FC_LD];  // [m][k], 18 KB
    __shared__ float Bs[128 * FC_LD];  // [n][k], 18 KB

    const int tid = threadIdx.x;
    const int lane = tid & 31;
    const int wid = tid >> 5;
    const int g = lane >> 2;       // group id (rows)
    const int c = lane & 3;        // thread-in-group (cols)
    const int mw = (wid >> 2) * 64;
    const int nw = (wid & 3) * 32;
    const int mBase = blockIdx.x * 128;
    const int nBase = blockIdx.y * 128;

    float acc[4][4][4];
#pragma unroll
    for (int mt = 0; mt < 4; ++mt)
#pragma unroll
        for (int nt = 0; nt < 4; ++nt)
#pragma unroll
            for (int i = 0; i < 4; ++i) acc[mt][nt][i] = 0.f;

    const float4 z4 = make_float4(0.f, 0.f, 0.f, 0.f);

    // loader: 1024 float4 per tile pair half; idx covers 128 rows x 8 float4
    float4 ar[4], br[4];
#pragma unroll
    for (int r = 0; r < 4; ++r) {
        const int idx = tid + r * 256;
        const int row = idx >> 3;
        const int kq = (idx & 7) << 2;
        ar[r] = *(const float4*)(g_A + (size_t)(mBase + row) * KFC + kq);
        const int n = nBase + row;
        br[r] = (n < V_) ? *(const float4*)(fc_W + (size_t)n * KFC + kq) : z4;
    }
#pragma unroll
    for (int r = 0; r < 4; ++r) {
        const int idx = tid + r * 256;
        const int row = idx >> 3;
        const int kq = (idx & 7) << 2;
        *(float4*)(As + row * FC_LD + kq) = ar[r];
        *(float4*)(Bs + row * FC_LD + kq) = br[r];
    }
    __syncthreads();

    for (int s = 0; s < KFC / 32; ++s) {
        // prefetch next stage into registers (overlaps with compute)
        if (s < KFC / 32 - 1) {
            const int k0 = (s + 1) * 32;
#pragma unroll
            for (int r = 0; r < 4; ++r) {
                const int idx = tid + r * 256;
                const int row = idx >> 3;
                const int kq = (idx & 7) << 2;
                ar[r] = *(const float4*)(g_A + (size_t)(mBase + row) * KFC + k0 + kq);
                const int n = nBase + row;
                br[r] = (n < V_) ? *(const float4*)(fc_W + (size_t)n * KFC + k0 + kq) : z4;
            }
        }

#pragma unroll
        for (int k8 = 0; k8 < 4; ++k8) {
            const int kk = k8 * 8;
            uint32_t ahi[4][4], alo[4][4];
#pragma unroll
            for (int mt = 0; mt < 4; ++mt) {
                const float* Ap = As + (mw + mt * 16 + g) * FC_LD + kk + c;
                split_tf32(Ap[0],           ahi[mt][0], alo[mt][0]);
                split_tf32(Ap[8 * FC_LD],   ahi[mt][1], alo[mt][1]);
                split_tf32(Ap[4],           ahi[mt][2], alo[mt][2]);
                split_tf32(Ap[8 * FC_LD+4], ahi[mt][3], alo[mt][3]);
            }
            uint32_t bhi[4][2], blo[4][2];
#pragma unroll
            for (int nt = 0; nt < 4; ++nt) {
                const float* Bp = Bs + (nw + nt * 8 + g) * FC_LD + kk + c;
                split_tf32(Bp[0], bhi[nt][0], blo[nt][0]);
                split_tf32(Bp[4], bhi[nt][1], blo[nt][1]);
            }
#pragma unroll
            for (int mt = 0; mt < 4; ++mt)
#pragma unroll
                for (int nt = 0; nt < 4; ++nt) {
                    mma_tf32(acc[mt][nt], ahi[mt], bhi[nt]);
                    mma_tf32(acc[mt][nt], alo[mt], bhi[nt]);
                    mma_tf32(acc[mt][nt], ahi[nt == 0 ? mt : mt], blo[nt]);
                }
        }
        __syncthreads();
        if (s < KFC / 32 - 1) {
#pragma unroll
            for (int r = 0; r < 4; ++r) {
                const int idx = tid + r * 256;
                const int row = idx >> 3;
                const int kq = (idx & 7) << 2;
                *(float4*)(As + row * FC_LD + kq) = ar[r];
                *(float4*)(Bs + row * FC_LD + kq) = br[r];
            }
            __syncthreads();
        }
    }

    // epilogue: c0/c1 -> (row g, cols 2c,2c+1), c2/c3 -> (row g+8)
#pragma unroll
    for (int mt = 0; mt < 4; ++mt) {
        const int m0 = mBase + mw + mt * 16 + g;
#pragma unroll
        for (int nt = 0; nt < 4; ++nt) {
            const int n0 = nBase + nw + nt * 8 + c * 2;
            if (n0 < V_) {
                const float2 b2 = *(const float2*)(fc_b + n0);
                float* p0 = out + (size_t)m0 * V_ + n0;
                p0[0] = acc[mt][nt][0] + b2.x;
                p0[1] = acc[mt][nt][1] + b2.y;
                float* p1 = out + (size_t)(m0 + 8) * V_ + n0;
                p1[0] = acc[mt][nt][2] + b2.x;
                p1[1] = acc[mt][nt][3] + b2.y;
            }
        }
    }
}

// ---------------------------------------------------------------------------
// Kernel 5: h_last -> tail of output
// ---------------------------------------------------------------------------
__global__ void k_hlast(float* __restrict__ out)
{
    const int idx = blockIdx.x * blockDim.x + threadIdx.x;
    if (idx < U_ * H_)
        out[(size_t)S_ * U_ * V_ + idx] = g_out[(size_t)(S_ - 1) * U_ * H_ + idx];
}

// ---------------------------------------------------------------------------
// Launch
// ---------------------------------------------------------------------------
extern "C" void kernel_launch(void* const* d_in, const int* in_sizes, int n_in,
                              void* d_out, int out_size)
{
    (void)in_sizes; (void)n_in; (void)out_size;
    const int*   x      = (const int*)  d_in[0];
    const float* t_in   = (const float*)d_in[1];
    const float* s_in   = (const float*)d_in[2];
    const float* h0     = (const float*)d_in[5];
    const int*   au     = (const int*)  d_in[6];
    const float* enc_W  = (const float*)d_in[7];
    const float* user_W = (const float*)d_in[8];
    const float* W_ih   = (const float*)d_in[9];
    const float* W_hh   = (const float*)d_in[10];
    const float* b_ih   = (const float*)d_in[11];
    const float* b_hh   = (const float*)d_in[12];
    const float* fc_W   = (const float*)d_in[13];
    const float* fc_b   = (const float*)d_in[14];
    float* out = (float*)d_out;

    k_gi<<<dim3(MTOT / 64, H3_ / 64), 256>>>(x, enc_W, W_ih, b_ih);
    k_gru<<<U_ / 4, 256>>>(h0, W_hh, b_hh);
    k_hlast<<<(U_ * H_ + 255) / 256, 256>>>(out);
    k_outw<<<dim3(S_, U_), 128>>>(t_in, s_in, au, user_W);
    k_fc_tc<<<dim3(MTOT / 128, (V_ + 127) / 128), 256>>>(fc_W, fc_b, out);
}

// round 8
// speedup vs baseline: 2.0490x; 1.1302x over previous
#include <cuda_runtime.h>
#include <cuda_bf16.h>
#include <math.h>
#include <stdint.h>

// Problem constants
#define S_   100
#define U_   128
#define H_   256
#define V_   10000
#define H3_  768
#define MTOT (S_ * U_)        // 12800
#define KFC  (2 * H_)         // 512

// Scratch (device globals; no dynamic allocation allowed)
__device__ float g_GI[MTOT * H3_];          // (S*U, 3H) input-side gates
__device__ float g_out[MTOT * H_];          // (S, U, H) GRU outputs
__device__ __nv_bfloat16 g_Ahi[(size_t)MTOT * KFC];  // A hi bf16
__device__ __nv_bfloat16 g_Alo[(size_t)MTOT * KFC];  // A lo bf16
__device__ __nv_bfloat16 g_Bhi[(size_t)V_ * KFC];    // fc_W hi bf16
__device__ __nv_bfloat16 g_Blo[(size_t)V_ * KFC];    // fc_W lo bf16

// ---------------------------------------------------------------------------
// Helpers
// ---------------------------------------------------------------------------
__device__ __forceinline__ void fma2(unsigned long long& d,
                                     unsigned long long a,
                                     unsigned long long b)
{
    asm("fma.rn.f32x2 %0, %1, %2, %0;" : "+l"(d) : "l"(a), "l"(b));
}

__device__ __forceinline__ float hsum2(unsigned long long v)
{
    float lo, hi;
    asm("mov.b64 {%0,%1}, %2;" : "=f"(lo), "=f"(hi) : "l"(v));
    return lo + hi;
}

__device__ __forceinline__ void split_bf16(float v, __nv_bfloat16& h, __nv_bfloat16& l)
{
    h = __float2bfloat16_rn(v);
    l = __float2bfloat16_rn(v - __bfloat162float(h));
}

__device__ __forceinline__ void ldsm_x4(uint32_t addr, uint32_t* r)
{
    asm volatile("ldmatrix.sync.aligned.m8n8.x4.shared.b16 {%0,%1,%2,%3}, [%4];"
                 : "=r"(r[0]), "=r"(r[1]), "=r"(r[2]), "=r"(r[3]) : "r"(addr));
}

__device__ __forceinline__ void mma_bf16(float* d, const uint32_t* a, uint32_t b0, uint32_t b1)
{
    asm volatile(
        "mma.sync.aligned.m16n8k16.row.col.f32.bf16.bf16.f32 "
        "{%0,%1,%2,%3},{%4,%5,%6,%7},{%8,%9},{%0,%1,%2,%3};"
        : "+f"(d[0]), "+f"(d[1]), "+f"(d[2]), "+f"(d[3])
        : "r"(a[0]), "r"(a[1]), "r"(a[2]), "r"(a[3]), "r"(b0), "r"(b1));
}

// ---------------------------------------------------------------------------
// Kernel 0: split fc_W into bf16 hi/lo (row-major (V, 512))
// ---------------------------------------------------------------------------
__global__ __launch_bounds__(256) void k_splitB(const float* __restrict__ W)
{
    const size_t i = ((size_t)blockIdx.x * 256 + threadIdx.x) * 8;
    if (i >= (size_t)V_ * KFC) return;
    float4 v0 = *(const float4*)(W + i);
    float4 v1 = *(const float4*)(W + i + 4);
    __align__(16) __nv_bfloat16 h[8], l[8];
    split_bf16(v0.x, h[0], l[0]); split_bf16(v0.y, h[1], l[1]);
    split_bf16(v0.z, h[2], l[2]); split_bf16(v0.w, h[3], l[3]);
    split_bf16(v1.x, h[4], l[4]); split_bf16(v1.y, h[5], l[5]);
    split_bf16(v1.z, h[6], l[6]); split_bf16(v1.w, h[7], l[7]);
    *(uint4*)(g_Bhi + i) = *(uint4*)h;
    *(uint4*)(g_Blo + i) = *(uint4*)l;
}

// ---------------------------------------------------------------------------
// Kernel 1: GI = gather(enc_W, x) @ W_ih^T + b_ih  (fp32 SIMT)
// ---------------------------------------------------------------------------
__global__ __launch_bounds__(256) void k_gi(
    const int* __restrict__ x,
    const float* __restrict__ enc_W,
    const float* __restrict__ W_ih,
    const float* __restrict__ b_ih)
{
    __shared__ float As[16][68];
    __shared__ float Bs[16][68];
    __shared__ int rowIdx[64];

    const int tid = threadIdx.x;
    const int mBase = blockIdx.x * 64;
    const int nBase = blockIdx.y * 64;

    if (tid < 64) rowIdx[tid] = x[mBase + tid];
    __syncthreads();

    const int tr = tid / 16;
    const int tc = tid % 16;
    const int lr = tid / 4;
    const int lq = tid % 4;

    float acc[4][4];
#pragma unroll
    for (int r = 0; r < 4; ++r)
#pragma unroll
        for (int c = 0; c < 4; ++c) acc[r][c] = 0.f;

    const int arow = rowIdx[lr];

    for (int k0 = 0; k0 < H_; k0 += 16) {
        float4 av = *(const float4*)(enc_W + (size_t)arow * H_ + k0 + lq * 4);
        float4 bv = *(const float4*)(W_ih + (size_t)(nBase + lr) * H_ + k0 + lq * 4);
        __syncthreads();
        As[lq * 4 + 0][lr] = av.x; As[lq * 4 + 1][lr] = av.y;
        As[lq * 4 + 2][lr] = av.z; As[lq * 4 + 3][lr] = av.w;
        Bs[lq * 4 + 0][lr] = bv.x; Bs[lq * 4 + 1][lr] = bv.y;
        Bs[lq * 4 + 2][lr] = bv.z; Bs[lq * 4 + 3][lr] = bv.w;
        __syncthreads();
#pragma unroll
        for (int k = 0; k < 16; ++k) {
            float a[4], b[4];
#pragma unroll
            for (int r = 0; r < 4; ++r) a[r] = As[k][tr * 4 + r];
#pragma unroll
            for (int c = 0; c < 4; ++c) b[c] = Bs[k][tc * 4 + c];
#pragma unroll
            for (int r = 0; r < 4; ++r)
#pragma unroll
                for (int c = 0; c < 4; ++c) acc[r][c] += a[r] * b[c];
        }
    }

#pragma unroll
    for (int r = 0; r < 4; ++r) {
        const int m = mBase + tr * 4 + r;
        float* row = g_GI + (size_t)m * H3_;
#pragma unroll
        for (int c = 0; c < 4; ++c) {
            const int n = nBase + tc * 4 + c;
            row[n] = acc[r][c] + b_ih[n];
        }
    }
}

// ---------------------------------------------------------------------------
// Kernel 2: GRU scan (packed f32x2 FMA phase-1)
// ---------------------------------------------------------------------------
__global__ __launch_bounds__(256) void k_gru(
    const float* __restrict__ h0,
    const float* __restrict__ W_hh,
    const float* __restrict__ b_hh)
{
    const int u0 = blockIdx.x * 4;
    const int tid = threadIdx.x;

    __shared__ float hs[4][H_];
    __shared__ float ghs[4][H3_];

    for (int i = tid; i < 4 * H_; i += 256) {
        const int u = i / H_, k = i % H_;
        hs[u][k] = h0[(size_t)(u0 + u) * H_ + k];
    }
    __syncthreads();

    const ulonglong2* W0 = (const ulonglong2*)(W_hh + (size_t)(tid)       * H_);
    const ulonglong2* W1 = (const ulonglong2*)(W_hh + (size_t)(tid + 256) * H_);
    const ulonglong2* W2 = (const ulonglong2*)(W_hh + (size_t)(tid + 512) * H_);
    const float bh0 = b_hh[tid], bh1 = b_hh[tid + 256], bh2 = b_hh[tid + 512];

    const int uu = tid >> 6;
    const int kk = (tid & 63) * 4;

    for (int t = 0; t < S_; ++t) {
        unsigned long long a0[4] = {0ull, 0ull, 0ull, 0ull};
        unsigned long long a1[4] = {0ull, 0ull, 0ull, 0ull};
        unsigned long long a2[4] = {0ull, 0ull, 0ull, 0ull};

#pragma unroll 4
        for (int k4 = 0; k4 < H_ / 4; ++k4) {
            ulonglong2 w0 = W0[k4], w1 = W1[k4], w2 = W2[k4];
#pragma unroll
            for (int u = 0; u < 4; ++u) {
                ulonglong2 h4 = *(const ulonglong2*)&hs[u][k4 * 4];
                fma2(a0[u], w0.x, h4.x); fma2(a0[u], w0.y, h4.y);
                fma2(a1[u], w1.x, h4.x); fma2(a1[u], w1.y, h4.y);
                fma2(a2[u], w2.x, h4.x); fma2(a2[u], w2.y, h4.y);
            }
        }
#pragma unroll
        for (int u = 0; u < 4; ++u) {
            ghs[u][tid]       = hsum2(a0[u]) + bh0;
            ghs[u][tid + 256] = hsum2(a1[u]) + bh1;
            ghs[u][tid + 512] = hsum2(a2[u]) + bh2;
        }
        __syncthreads();

        const float* GIrow = g_GI + ((size_t)t * U_ + (u0 + uu)) * H3_;
        float4 ir = *(const float4*)(GIrow + kk);
        float4 iz = *(const float4*)(GIrow + H_ + kk);
        float4 in4 = *(const float4*)(GIrow + 2 * H_ + kk);
        float4 hr = *(const float4*)&ghs[uu][kk];
        float4 hz = *(const float4*)&ghs[uu][H_ + kk];
        float4 hn = *(const float4*)&ghs[uu][2 * H_ + kk];
        float4 hp = *(const float4*)&hs[uu][kk];

        float4 hnew;
        {
            float r = 1.f / (1.f + expf(-(ir.x + hr.x)));
            float z = 1.f / (1.f + expf(-(iz.x + hz.x)));
            float n = tanhf(in4.x + r * hn.x);
            hnew.x = (1.f - z) * n + z * hp.x;
        }
        {
            float r = 1.f / (1.f + expf(-(ir.y + hr.y)));
            float z = 1.f / (1.f + expf(-(iz.y + hz.y)));
            float n = tanhf(in4.y + r * hn.y);
            hnew.y = (1.f - z) * n + z * hp.y;
        }
        {
            float r = 1.f / (1.f + expf(-(ir.z + hr.z)));
            float z = 1.f / (1.f + expf(-(iz.z + hz.z)));
            float n = tanhf(in4.z + r * hn.z);
            hnew.z = (1.f - z) * n + z * hp.z;
        }
        {
            float r = 1.f / (1.f + expf(-(ir.w + hr.w)));
            float z = 1.f / (1.f + expf(-(iz.w + hz.w)));
            float n = tanhf(in4.w + r * hn.w);
            hnew.w = (1.f - z) * n + z * hp.w;
        }

        *(float4*)&hs[uu][kk] = hnew;
        *(float4*)(g_out + ((size_t)t * U_ + (u0 + uu)) * H_ + kk) = hnew;
        __syncthreads();
    }
}

// ---------------------------------------------------------------------------
// Kernel 3: causal ST weights + weighted sum -> A hi/lo bf16 (fused split)
// ---------------------------------------------------------------------------
__global__ __launch_bounds__(128) void k_outw(
    const float* __restrict__ t_in,
    const float* __restrict__ s_in,
    const int* __restrict__ active_user,
    const float* __restrict__ user_W)
{
    const int i = blockIdx.x;
    const int u = blockIdx.y;
    const int tid = threadIdx.x;

    __shared__ float w[S_];

    const float ti = t_in[i * U_ + u];
    const float si0 = s_in[(i * U_ + u) * 2 + 0];
    const float si1 = s_in[(i * U_ + u) * 2 + 1];

    if (tid <= i && tid < S_) {
        const int j = tid;
        const float dt = ti - t_in[j * U_ + u];
        const float dx = si0 - s_in[(j * U_ + u) * 2 + 0];
        const float dy = si1 - s_in[(j * U_ + u) * 2 + 1];
        const float dist = sqrtf(dx * dx + dy * dy);
        const float a = (cosf(dt * (6.2831853071795864f / 86400.f)) + 1.f) * 0.5f
                        * expf(dt * (-0.1f / 86400.f));
        const float b = expf(-dist * 100.f);
        w[j] = a * b + 1e-10f;
    }
    __syncthreads();

    float sum = 0.f;
    for (int j = 0; j <= i; ++j) sum += w[j];
    const float inv = 1.f / sum;

    float acc0 = 0.f, acc1 = 0.f;
    for (int j = 0; j <= i; ++j) {
        const float wj = w[j];
        const float* orow = g_out + ((size_t)j * U_ + u) * H_;
        acc0 += wj * orow[tid];
        acc1 += wj * orow[tid + 128];
    }

    const size_t m = (size_t)i * U_ + u;
    const float* pu = user_W + (size_t)active_user[u] * H_;

    float vals[4];
    vals[0] = acc0 * inv;
    vals[1] = acc1 * inv;
    vals[2] = pu[tid];
    vals[3] = pu[tid + 128];
    const int idxs[4] = {tid, tid + 128, 256 + tid, 384 + tid};
#pragma unroll
    for (int q = 0; q < 4; ++q) {
        __nv_bfloat16 h, l;
        split_bf16(vals[q], h, l);
        g_Ahi[m * KFC + idxs[q]] = h;
        g_Alo[m * KFC + idxs[q]] = l;
    }
}

// ---------------------------------------------------------------------------
// Kernel 4: y = A @ fc_W^T + fc_b, 3x-bf16 mma.sync.m16n8k16.
// M=12800, N=10000, K=512. Block tile 128x128, BK=32, 8 warps x (64x32).
// Smem rows padded to 40 bf16 -> conflict-free ldmatrix.
// ---------------------------------------------------------------------------
#define FLD 40   // bf16 elements per smem row (32 data + 8 pad)

__global__ __launch_bounds__(256, 1) void k_fc_bf16(
    const float* __restrict__ fc_b,
    float* __restrict__ out)
{
    __shared__ __nv_bfloat16 Ahs[128 * FLD];
    __shared__ __nv_bfloat16 Als[128 * FLD];
    __shared__ __nv_bfloat16 Bhs[128 * FLD];
    __shared__ __nv_bfloat16 Bls[128 * FLD];

    const int tid = threadIdx.x;
    const int lane = tid & 31;
    const int wid = tid >> 5;
    const int g = lane >> 2;
    const int c = lane & 3;
    const int mw = (wid >> 2) * 64;
    const int nw = (wid & 3) * 32;
    const int mBase = blockIdx.x * 128;
    const int nBase = blockIdx.y * 128;

    float acc[4][4][4];
#pragma unroll
    for (int mt = 0; mt < 4; ++mt)
#pragma unroll
        for (int nt = 0; nt < 4; ++nt)
#pragma unroll
            for (int i = 0; i < 4; ++i) acc[mt][nt][i] = 0.f;

    // ldmatrix address setup
    const int lrow = lane & 15;
    const int lcol = (lane >> 4) * 8;
    const uint32_t sAh = (uint32_t)__cvta_generic_to_shared(Ahs);
    const uint32_t sAl = (uint32_t)__cvta_generic_to_shared(Als);
    const uint32_t sBh = (uint32_t)__cvta_generic_to_shared(Bhs);
    const uint32_t sBl = (uint32_t)__cvta_generic_to_shared(Bls);
    uint32_t offA[4], offB[2];
#pragma unroll
    for (int mt = 0; mt < 4; ++mt)
        offA[mt] = (uint32_t)(((mw + mt * 16 + lrow) * FLD + lcol) * 2);
#pragma unroll
    for (int np = 0; np < 2; ++np)
        offB[np] = (uint32_t)(((nw + np * 16 + lrow) * FLD + lcol) * 2);

    const uint4 z4 = make_uint4(0u, 0u, 0u, 0u);

    // loader mapping: 512 uint4 per array (128 rows x 4 quads of 8 bf16)
    uint4 avh[2], avl[2], bvh[2], bvl[2];
#pragma unroll
    for (int r = 0; r < 2; ++r) {
        const int idx = tid + r * 256;
        const int row = idx >> 2;
        const int kq = (idx & 3) * 8;
        const size_t aoff = (size_t)(mBase + row) * KFC + kq;
        avh[r] = *(const uint4*)(g_Ahi + aoff);
        avl[r] = *(const uint4*)(g_Alo + aoff);
        const int n = nBase + row;
        const size_t boff = (size_t)n * KFC + kq;
        bvh[r] = (n < V_) ? *(const uint4*)(g_Bhi + boff) : z4;
        bvl[r] = (n < V_) ? *(const uint4*)(g_Blo + boff) : z4;
    }
#pragma unroll
    for (int r = 0; r < 2; ++r) {
        const int idx = tid + r * 256;
        const int row = idx >> 2;
        const int kq = (idx & 3) * 8;
        *(uint4*)(Ahs + row * FLD + kq) = avh[r];
        *(uint4*)(Als + row * FLD + kq) = avl[r];
        *(uint4*)(Bhs + row * FLD + kq) = bvh[r];
        *(uint4*)(Bls + row * FLD + kq) = bvl[r];
    }
    __syncthreads();

    for (int s = 0; s < KFC / 32; ++s) {
        if (s < KFC / 32 - 1) {
            const int k0 = (s + 1) * 32;
#pragma unroll
            for (int r = 0; r < 2; ++r) {
                const int idx = tid + r * 256;
                const int row = idx >> 2;
                const int kq = (idx & 3) * 8;
                const size_t aoff = (size_t)(mBase + row) * KFC + k0 + kq;
                avh[r] = *(const uint4*)(g_Ahi + aoff);
                avl[r] = *(const uint4*)(g_Alo + aoff);
                const int n = nBase + row;
                const size_t boff = (size_t)n * KFC + k0 + kq;
                bvh[r] = (n < V_) ? *(const uint4*)(g_Bhi + boff) : z4;
                bvl[r] = (n < V_) ? *(const uint4*)(g_Blo + boff) : z4;
            }
        }

#pragma unroll
        for (int j = 0; j < 2; ++j) {
            const uint32_t jb = j * 32;  // 16 bf16 = 32 bytes
            uint32_t ah[4][4], al[4][4], bh[2][4], bl[2][4];
#pragma unroll
            for (int mt = 0; mt < 4; ++mt) {
                ldsm_x4(sAh + offA[mt] + jb, ah[mt]);
                ldsm_x4(sAl + offA[mt] + jb, al[mt]);
            }
#pragma unroll
            for (int np = 0; np < 2; ++np) {
                ldsm_x4(sBh + offB[np] + jb, bh[np]);
                ldsm_x4(sBl + offB[np] + jb, bl[np]);
            }
            // pass 1: hi * hi
#pragma unroll
            for (int mt = 0; mt < 4; ++mt)
#pragma unroll
                for (int nt = 0; nt < 4; ++nt)
                    mma_bf16(acc[mt][nt], ah[mt], bh[nt >> 1][nt & 1], bh[nt >> 1][2 + (nt & 1)]);
            // pass 2: hi * lo
#pragma unroll
            for (int mt = 0; mt < 4; ++mt)
#pragma unroll
                for (int nt = 0; nt < 4; ++nt)
                    mma_bf16(acc[mt][nt], ah[mt], bl[nt >> 1][nt & 1], bl[nt >> 1][2 + (nt & 1)]);
            // pass 3: lo * hi
#pragma unroll
            for (int mt = 0; mt < 4; ++mt)
#pragma unroll
                for (int nt = 0; nt < 4; ++nt)
                    mma_bf16(acc[mt][nt], al[mt], bh[nt >> 1][nt & 1], bh[nt >> 1][2 + (nt & 1)]);
        }
        __syncthreads();
        if (s < KFC / 32 - 1) {
#pragma unroll
            for (int r = 0; r < 2; ++r) {
                const int idx = tid + r * 256;
                const int row = idx >> 2;
                const int kq = (idx & 3) * 8;
                *(uint4*)(Ahs + row * FLD + kq) = avh[r];
                *(uint4*)(Als + row * FLD + kq) = avl[r];
                *(uint4*)(Bhs + row * FLD + kq) = bvh[r];
                *(uint4*)(Bls + row * FLD + kq) = bvl[r];
            }
            __syncthreads();
        }
    }

    // epilogue: c0,c1 -> (row g, cols 2c,2c+1); c2,c3 -> (row g+8)
#pragma unroll
    for (int mt = 0; mt < 4; ++mt) {
        const int m0 = mBase + mw + mt * 16 + g;
#pragma unroll
        for (int nt = 0; nt < 4; ++nt) {
            const int n0 = nBase + nw + nt * 8 + c * 2;
            if (n0 < V_) {
                const float2 b2 = *(const float2*)(fc_b + n0);
                float* p0 = out + (size_t)m0 * V_ + n0;
                p0[0] = acc[mt][nt][0] + b2.x;
                p0[1] = acc[mt][nt][1] + b2.y;
                float* p1 = out + (size_t)(m0 + 8) * V_ + n0;
                p1[0] = acc[mt][nt][2] + b2.x;
                p1[1] = acc[mt][nt][3] + b2.y;
            }
        }
    }
}

// ---------------------------------------------------------------------------
// Kernel 5: h_last -> tail of output
// ---------------------------------------------------------------------------
__global__ void k_hlast(float* __restrict__ out)
{
    const int idx = blockIdx.x * blockDim.x + threadIdx.x;
    if (idx < U_ * H_)
        out[(size_t)S_ * U_ * V_ + idx] = g_out[(size_t)(S_ - 1) * U_ * H_ + idx];
}

// ---------------------------------------------------------------------------
// Launch
// ---------------------------------------------------------------------------
extern "C" void kernel_launch(void* const* d_in, const int* in_sizes, int n_in,
                              void* d_out, int out_size)
{
    (void)in_sizes; (void)n_in; (void)out_size;
    const int*   x      = (const int*)  d_in[0];
    const float* t_in   = (const float*)d_in[1];
    const float* s_in   = (const float*)d_in[2];
    const float* h0     = (const float*)d_in[5];
    const int*   au     = (const int*)  d_in[6];
    const float* enc_W  = (const float*)d_in[7];
    const float* user_W = (const float*)d_in[8];
    const float* W_ih   = (const float*)d_in[9];
    const float* W_hh   = (const float*)d_in[10];
    const float* b_ih   = (const float*)d_in[11];
    const float* b_hh   = (const float*)d_in[12];
    const float* fc_W   = (const float*)d_in[13];
    const float* fc_b   = (const float*)d_in[14];
    float* out = (float*)d_out;

    k_splitB<<<(V_ * KFC / 8 + 255) / 256, 256>>>(fc_W);
    k_gi<<<dim3(MTOT / 64, H3_ / 64), 256>>>(x, enc_W, W_ih, b_ih);
    k_gru<<<U_ / 4, 256>>>(h0, W_hh, b_hh);
    k_hlast<<<(U_ * H_ + 255) / 256, 256>>>(out);
    k_outw<<<dim3(S_, U_), 128>>>(t_in, s_in, au, user_W);
    k_fc_bf16<<<dim3(MTOT / 128, (V_ + 127) / 128), 256>>>(fc_b, out);
}